// round 3
// baseline (speedup 1.0000x reference)
#include <cuda_runtime.h>
#include <cuda_bf16.h>
#include <math.h>

#define MAX_N 50000
#define MAX_E 800000
#define D 128
#define C 40

// ---------------- static scratch ----------------
__device__ int   g_cnt[MAX_N];        // in-degree (by dst) for CSR
__device__ int   g_degc[MAX_N];       // out-degree (by src) for normalization
__device__ int   g_rowptr[MAX_N + 1];
__device__ int   g_off[MAX_N];        // working offsets for scatter
__device__ int   g_csrc[MAX_E];       // CSR: source node per edge (grouped by dst)
__device__ float g_csw[MAX_E];        // CSR: edge weight
__device__ float g_dinv[MAX_N];       // deg^{-1/2}
__device__ float g_tx1[MAX_N * D];
__device__ float g_tx2[MAX_N * D];
__device__ float g_h[MAX_N * D];

// ---------------- graph prep ----------------
__global__ void k_zero(int n) {
    int i = blockIdx.x * blockDim.x + threadIdx.x;
    if (i < n) { g_cnt[i] = 0; g_degc[i] = 0; }
}

__global__ void k_count(const int* __restrict__ ei, int E) {
    int e = blockIdx.x * blockDim.x + threadIdx.x;
    if (e < E) {
        atomicAdd(&g_degc[ei[e]], 1);      // src degree (normalization)
        atomicAdd(&g_cnt[ei[E + e]], 1);   // dst degree (CSR)
    }
}

__global__ void k_dinv(int n) {
    int i = blockIdx.x * blockDim.x + threadIdx.x;
    if (i < n) {
        int d = g_degc[i];
        g_dinv[i] = (d > 0) ? rsqrtf((float)d) : 0.0f;
    }
}

// single-block exclusive scan of g_cnt -> g_rowptr (and copy to g_off)
__global__ void k_scan(int n) {
    __shared__ int ssum[1024];
    int t = threadIdx.x;
    int chunk = (n + 1023) >> 10;
    int beg = t * chunk;
    int end = min(beg + chunk, n);
    int s = 0;
    for (int i = beg; i < end; ++i) s += g_cnt[i];
    ssum[t] = s;
    __syncthreads();
    for (int off = 1; off < 1024; off <<= 1) {
        int v = (t >= off) ? ssum[t - off] : 0;
        __syncthreads();
        ssum[t] += v;
        __syncthreads();
    }
    int pre = (t == 0) ? 0 : ssum[t - 1];
    for (int i = beg; i < end; ++i) {
        g_rowptr[i] = pre;
        g_off[i] = pre;
        pre += g_cnt[i];
    }
    if (beg < n && end == n) g_rowptr[n] = pre;
}

__global__ void k_scatter(const int* __restrict__ ei, int E) {
    int e = blockIdx.x * blockDim.x + threadIdx.x;
    if (e < E) {
        int s = ei[e];
        int t = ei[E + e];
        int p = atomicAdd(&g_off[t], 1);
        g_csrc[p] = s;
        g_csw[p] = -g_dinv[s] * g_dinv[t];
    }
}

// ---------------- SpMV (gather, no float atomics) ----------------
// One warp per node. Lane l covers features [4l, 4l+4).
// hout[i] = scale * sum_j w_j * hin[src_j]   (- sub[i] if sub != null)
__global__ void k_spmv(const float* __restrict__ hin, float* __restrict__ hout,
                       const float* __restrict__ sub, float scale, int n) {
    int node = blockIdx.x * (blockDim.x >> 5) + (threadIdx.x >> 5);
    int lane = threadIdx.x & 31;
    if (node >= n) return;
    int beg = g_rowptr[node];
    int end = g_rowptr[node + 1];
    float4 acc = make_float4(0.f, 0.f, 0.f, 0.f);
    for (int j = beg; j < end; ++j) {
        int s = g_csrc[j];
        float w = g_csw[j];
        float4 v = *(const float4*)(hin + (size_t)s * D + lane * 4);
        acc.x += w * v.x; acc.y += w * v.y; acc.z += w * v.z; acc.w += w * v.w;
    }
    float4 r;
    if (sub) {
        float4 u = *(const float4*)(sub + (size_t)node * D + lane * 4);
        r = make_float4(scale * acc.x - u.x, scale * acc.y - u.y,
                        scale * acc.z - u.z, scale * acc.w - u.w);
    } else {
        r = acc;
    }
    *(float4*)(hout + (size_t)node * D + lane * 4) = r;
}

// ---------------- layer-1 fused GEMM: h = relu([x|Tx1|Tx2] @ W1cat + b1) ----------------
__global__ void k_gemm1(const float* __restrict__ x, const float* __restrict__ W1,
                        const float* __restrict__ b1, int n) {
    __shared__ float As[64][33];
    __shared__ float Ws[32][128];

    int tid = threadIdx.x;
    int tx = tid & 15;
    int ty = tid >> 4;
    int row0 = blockIdx.x * 64;

    const float* Aptr[3] = { x, g_tx1, g_tx2 };

    float acc[4][8];
#pragma unroll
    for (int i = 0; i < 4; ++i)
#pragma unroll
        for (int j = 0; j < 8; ++j) acc[i][j] = 0.0f;

    for (int ch = 0; ch < 12; ++ch) {
        int term = ch >> 2;
        int coff = (ch & 3) * 32;
        const float* A = Aptr[term];

#pragma unroll
        for (int q = 0; q < 2; ++q) {
            int idx = tid + q * 256;
            int r = idx >> 3;
            int c4 = (idx & 7) * 4;
            int grow = row0 + r;
            float4 v = (grow < n)
                ? *(const float4*)(A + (size_t)grow * D + coff + c4)
                : make_float4(0.f, 0.f, 0.f, 0.f);
            As[r][c4 + 0] = v.x;
            As[r][c4 + 1] = v.y;
            As[r][c4 + 2] = v.z;
            As[r][c4 + 3] = v.w;
        }
#pragma unroll
        for (int q = 0; q < 4; ++q) {
            int idx = tid + q * 256;
            int k = idx >> 5;
            int j4 = (idx & 31) * 4;
            *(float4*)&Ws[k][j4] =
                *(const float4*)(W1 + (size_t)term * D * D + (size_t)(coff + k) * D + j4);
        }
        __syncthreads();

#pragma unroll
        for (int k = 0; k < 32; ++k) {
            float a0 = As[ty * 4 + 0][k];
            float a1 = As[ty * 4 + 1][k];
            float a2 = As[ty * 4 + 2][k];
            float a3 = As[ty * 4 + 3][k];
            float4 w0 = *(float4*)&Ws[k][tx * 8];
            float4 w1 = *(float4*)&Ws[k][tx * 8 + 4];
            acc[0][0] += a0 * w0.x; acc[0][1] += a0 * w0.y; acc[0][2] += a0 * w0.z; acc[0][3] += a0 * w0.w;
            acc[0][4] += a0 * w1.x; acc[0][5] += a0 * w1.y; acc[0][6] += a0 * w1.z; acc[0][7] += a0 * w1.w;
            acc[1][0] += a1 * w0.x; acc[1][1] += a1 * w0.y; acc[1][2] += a1 * w0.z; acc[1][3] += a1 * w0.w;
            acc[1][4] += a1 * w1.x; acc[1][5] += a1 * w1.y; acc[1][6] += a1 * w1.z; acc[1][7] += a1 * w1.w;
            acc[2][0] += a2 * w0.x; acc[2][1] += a2 * w0.y; acc[2][2] += a2 * w0.z; acc[2][3] += a2 * w0.w;
            acc[2][4] += a2 * w1.x; acc[2][5] += a2 * w1.y; acc[2][6] += a2 * w1.z; acc[2][7] += a2 * w1.w;
            acc[3][0] += a3 * w0.x; acc[3][1] += a3 * w0.y; acc[3][2] += a3 * w0.z; acc[3][3] += a3 * w0.w;
            acc[3][4] += a3 * w1.x; acc[3][5] += a3 * w1.y; acc[3][6] += a3 * w1.z; acc[3][7] += a3 * w1.w;
        }
        __syncthreads();
    }

    int j0 = tx * 8;
#pragma unroll
    for (int i = 0; i < 4; ++i) {
        int grow = row0 + ty * 4 + i;
        if (grow < n) {
#pragma unroll
            for (int j = 0; j < 8; ++j) {
                float v = acc[i][j] + b1[j0 + j];
                g_h[(size_t)grow * D + j0 + j] = fmaxf(v, 0.0f);
            }
        }
    }
}

// ---------------- layer-2 fused GEMM + log_softmax ----------------
__global__ void k_gemm2(const float* __restrict__ W2, const float* __restrict__ b2,
                        float* __restrict__ out, int n) {
    __shared__ float As[32][33];
    __shared__ float Ws[32][40];
    __shared__ float zs[32][40];
    __shared__ float rl[32];

    int tid = threadIdx.x;
    int g = tid / 40;
    int j = tid % 40;
    int row0 = blockIdx.x * 32;

    const float* Aptr[3] = { g_h, g_tx1, g_tx2 };

    float acc[8];
#pragma unroll
    for (int r = 0; r < 8; ++r) acc[r] = 0.0f;

    for (int ch = 0; ch < 12; ++ch) {
        int term = ch >> 2;
        int coff = (ch & 3) * 32;
        const float* A = Aptr[term];

        for (int idx = tid; idx < 32 * 32; idx += 160) {
            int r = idx >> 5;
            int c = idx & 31;
            int grow = row0 + r;
            As[r][c] = (grow < n) ? A[(size_t)grow * D + coff + c] : 0.0f;
        }
        for (int idx = tid; idx < 32 * 40; idx += 160) {
            int k = idx / 40;
            int jj = idx % 40;
            Ws[k][jj] = W2[(size_t)term * D * C + (size_t)(coff + k) * C + jj];
        }
        __syncthreads();

#pragma unroll
        for (int k = 0; k < 32; ++k) {
            float w = Ws[k][j];
#pragma unroll
            for (int r = 0; r < 8; ++r) acc[r] += As[g * 8 + r][k] * w;
        }
        __syncthreads();
    }

    float bj = b2[j];
#pragma unroll
    for (int r = 0; r < 8; ++r) zs[g * 8 + r][j] = acc[r] + bj;
    __syncthreads();

    if (tid < 32) {
        float m = -INFINITY;
#pragma unroll
        for (int jj = 0; jj < C; ++jj) m = fmaxf(m, zs[tid][jj]);
        float s = 0.0f;
#pragma unroll
        for (int jj = 0; jj < C; ++jj) s += __expf(zs[tid][jj] - m);
        rl[tid] = m + logf(s);
    }
    __syncthreads();

#pragma unroll
    for (int r = 0; r < 8; ++r) {
        int lr = g * 8 + r;
        int grow = row0 + lr;
        if (grow < n) out[(size_t)grow * C + j] = zs[lr][j] - rl[lr];
    }
}

static float* sym_addr_f(const void* sym) {
    void* p = nullptr;
    cudaGetSymbolAddress(&p, sym);
    return (float*)p;
}

extern "C" void kernel_launch(void* const* d_in, const int* in_sizes, int n_in,
                              void* d_out, int out_size) {
    const float* x  = (const float*)d_in[0];
    const int*   ei = (const int*)d_in[1];     // int32 (JAX default x64 disabled)
    const float* W1 = (const float*)d_in[2];
    const float* b1 = (const float*)d_in[3];
    const float* W2 = (const float*)d_in[4];
    const float* b2 = (const float*)d_in[5];
    float*       out = (float*)d_out;

    int N = in_sizes[0] / D;
    int E = in_sizes[1] / 2;

    float* tx1 = sym_addr_f((const void*)g_tx1);
    float* tx2 = sym_addr_f((const void*)g_tx2);
    float* h   = sym_addr_f((const void*)g_h);

    dim3 b256(256);
    int gN  = (N + 255) / 256;
    int gE  = (E + 255) / 256;
    int gSp = (N * 32 + 255) / 256;   // warp per node
    int gG1 = (N + 63) / 64;
    int gG2 = (N + 31) / 32;

    // graph prep: degrees, dinv, CSR (by dst)
    k_zero<<<gN, b256>>>(N);
    k_count<<<gE, b256>>>(ei, E);
    k_dinv<<<gN, b256>>>(N);
    k_scan<<<1, 1024>>>(N);
    k_scatter<<<gE, b256>>>(ei, E);

    // layer 1: Tx1 = L~ x ; Tx2 = 2 L~ Tx1 - x
    k_spmv<<<gSp, b256>>>(x,   tx1, nullptr, 1.0f, N);
    k_spmv<<<gSp, b256>>>(tx1, tx2, x,       2.0f, N);
    k_gemm1<<<gG1, b256>>>(x, W1, b1, N);

    // layer 2: Tx1 = L~ h ; Tx2 = 2 L~ Tx1 - h
    k_spmv<<<gSp, b256>>>(h,   tx1, nullptr, 1.0f, N);
    k_spmv<<<gSp, b256>>>(tx1, tx2, h,       2.0f, N);
    k_gemm2<<<gG2, dim3(160)>>>(W2, b2, out, N);
}

// round 4
// speedup vs baseline: 1.5559x; 1.5559x over previous
#include <cuda_runtime.h>
#include <cuda_bf16.h>
#include <math.h>
#include <stdint.h>

#define MAX_N 50000
#define MAX_E 800000
#define D 128
#define C 40
#define NB 64               // max scan blocks (ceil(50000/1024)=49)

// ---------------- static scratch ----------------
__device__ int   g_cnt[MAX_N];
__device__ int   g_degc[MAX_N];
__device__ int   g_rowptr[MAX_N + 1];
__device__ int   g_off[MAX_N];
__device__ int   g_bsum[NB];
__device__ int   g_boff[NB];
__device__ int   g_csrc[MAX_E];
__device__ float g_csw[MAX_E];
__device__ float g_dinv[MAX_N];
__device__ float g_tx1[MAX_N * D];
__device__ float g_tx2[MAX_N * D];
__device__ float g_h[MAX_N * D];

__device__ __forceinline__ uint32_t f2tf32(float f) {
    uint32_t u;
    asm("cvt.rna.tf32.f32 %0, %1;" : "=r"(u) : "f"(f));
    return u;
}

// ---------------- graph prep ----------------
__global__ void k_zero(int n) {
    int i = blockIdx.x * blockDim.x + threadIdx.x;
    if (i < n) { g_cnt[i] = 0; g_degc[i] = 0; }
}

__global__ void k_count(const int* __restrict__ ei, int E) {
    int e = blockIdx.x * blockDim.x + threadIdx.x;
    if (e < E) {
        atomicAdd(&g_degc[ei[e]], 1);
        atomicAdd(&g_cnt[ei[E + e]], 1);
    }
}

__global__ void k_dinv(int n) {
    int i = blockIdx.x * blockDim.x + threadIdx.x;
    if (i < n) {
        int d = g_degc[i];
        g_dinv[i] = (d > 0) ? rsqrtf((float)d) : 0.0f;
    }
}

// scan stage 1: per-1024-chunk block sums (grid = nb, 256 thr, 4 elems/thr)
__global__ void k_scan1(int n) {
    int b = blockIdx.x, t = threadIdx.x;
    int base = b * 1024 + t * 4;
    int s = 0;
#pragma unroll
    for (int j = 0; j < 4; ++j) {
        int i = base + j;
        if (i < n) s += g_cnt[i];
    }
#pragma unroll
    for (int o = 16; o; o >>= 1) s += __shfl_down_sync(0xffffffffu, s, o);
    __shared__ int ws[8];
    if ((t & 31) == 0) ws[t >> 5] = s;
    __syncthreads();
    if (t == 0) {
        int tot = 0;
#pragma unroll
        for (int w = 0; w < 8; ++w) tot += ws[w];
        g_bsum[b] = tot;
    }
}

// scan stage 2: 1 warp scans nb block sums; writes rowptr[n] = total
__global__ void k_scan2(int nb, int n) {
    int t = threadIdx.x;   // 32 threads
    int v0 = (2 * t < nb) ? g_bsum[2 * t] : 0;
    int v1 = (2 * t + 1 < nb) ? g_bsum[2 * t + 1] : 0;
    int s = v0 + v1;
    int inc = s;
#pragma unroll
    for (int o = 1; o < 32; o <<= 1) {
        int u = __shfl_up_sync(0xffffffffu, inc, o);
        if (t >= o) inc += u;
    }
    int exc = inc - s;
    if (2 * t < nb) g_boff[2 * t] = exc;
    if (2 * t + 1 < nb) g_boff[2 * t + 1] = exc + v0;
    if (t == 31) g_rowptr[n] = inc;
}

// scan stage 3: rescan each chunk with its offset -> rowptr / off
__global__ void k_scan3(int n) {
    int b = blockIdx.x, t = threadIdx.x;
    int base = b * 1024 + t * 4;
    int v[4];
    int s = 0;
#pragma unroll
    for (int j = 0; j < 4; ++j) {
        int i = base + j;
        v[j] = (i < n) ? g_cnt[i] : 0;
        s += v[j];
    }
    int inc = s;
#pragma unroll
    for (int o = 1; o < 32; o <<= 1) {
        int u = __shfl_up_sync(0xffffffffu, inc, o);
        if ((t & 31) >= o) inc += u;
    }
    __shared__ int ws[8];
    __shared__ int wo[8];
    if ((t & 31) == 31) ws[t >> 5] = inc;
    __syncthreads();
    if (t == 0) {
        int p = 0;
#pragma unroll
        for (int w = 0; w < 8; ++w) { wo[w] = p; p += ws[w]; }
    }
    __syncthreads();
    int pre = g_boff[b] + wo[t >> 5] + (inc - s);
#pragma unroll
    for (int j = 0; j < 4; ++j) {
        int i = base + j;
        if (i < n) { g_rowptr[i] = pre; g_off[i] = pre; }
        pre += v[j];
    }
}

__global__ void k_scatter(const int* __restrict__ ei, int E) {
    int e = blockIdx.x * blockDim.x + threadIdx.x;
    if (e < E) {
        int s = ei[e];
        int t = ei[E + e];
        int p = atomicAdd(&g_off[t], 1);
        g_csrc[p] = s;
        g_csw[p] = -g_dinv[s] * g_dinv[t];
    }
}

// ---------------- SpMV (CSR gather) ----------------
__global__ void k_spmv(const float* __restrict__ hin, float* __restrict__ hout,
                       const float* __restrict__ sub, float scale, int n) {
    int node = blockIdx.x * (blockDim.x >> 5) + (threadIdx.x >> 5);
    int lane = threadIdx.x & 31;
    if (node >= n) return;
    int beg = g_rowptr[node];
    int end = g_rowptr[node + 1];
    float4 acc = make_float4(0.f, 0.f, 0.f, 0.f);
    for (int j = beg; j < end; ++j) {
        int s = g_csrc[j];
        float w = g_csw[j];
        float4 v = *(const float4*)(hin + (size_t)s * D + lane * 4);
        acc.x += w * v.x; acc.y += w * v.y; acc.z += w * v.z; acc.w += w * v.w;
    }
    float4 r;
    if (sub) {
        float4 u = *(const float4*)(sub + (size_t)node * D + lane * 4);
        r = make_float4(scale * acc.x - u.x, scale * acc.y - u.y,
                        scale * acc.z - u.z, scale * acc.w - u.w);
    } else {
        r = acc;
    }
    *(float4*)(hout + (size_t)node * D + lane * 4) = r;
}

// ---------------- layer-1 GEMM: tf32 tensor cores ----------------
// h = relu([x|Tx1|Tx2] @ W1cat + b1).  BM=128, BN=128, BK=32, 256 thr / 8 warps.
// Warp grid 4(m) x 2(n): warp tile 32x64 -> mma m16n8k8: 2 mtiles x 8 ntiles.
#define APAD 4      // A smem stride 36: fragment bank = 4g+t (conflict-free)
#define BPAD 8      // B smem stride 136: fragment bank = 8t+g (conflict-free)

__global__ void k_gemm1(const float* __restrict__ x, const float* __restrict__ W1,
                        const float* __restrict__ b1, int n) {
    __shared__ uint32_t As[128 * (32 + APAD)];
    __shared__ uint32_t Bs[32 * (128 + BPAD)];
    __shared__ float bsh[128];

    int tid = threadIdx.x;
    int wid = tid >> 5, lane = tid & 31;
    int wm = wid >> 1;          // 0..3
    int wn = wid & 1;           // 0..1
    int g = lane >> 2, tq = lane & 3;
    int row0 = blockIdx.x * 128;

    if (tid < 128) bsh[tid] = b1[tid];

    const float* Aptr[3] = { x, g_tx1, g_tx2 };

    float c[2][8][4];
#pragma unroll
    for (int mt = 0; mt < 2; ++mt)
#pragma unroll
        for (int nt = 0; nt < 8; ++nt)
#pragma unroll
            for (int q = 0; q < 4; ++q) c[mt][nt][q] = 0.0f;

    for (int ch = 0; ch < 12; ++ch) {
        int term = ch >> 2;
        int coff = (ch & 3) * 32;
        const float* A = Aptr[term];

        // A tile 128x32: 1024 float4 / 256 thr = 4 each
#pragma unroll
        for (int q = 0; q < 4; ++q) {
            int idx = tid + q * 256;
            int r = idx >> 3;
            int c4 = (idx & 7) * 4;
            int grow = row0 + r;
            float4 v = (grow < n)
                ? *(const float4*)(A + (size_t)grow * D + coff + c4)
                : make_float4(0.f, 0.f, 0.f, 0.f);
            uint32_t* p = &As[r * (32 + APAD) + c4];
            p[0] = f2tf32(v.x); p[1] = f2tf32(v.y);
            p[2] = f2tf32(v.z); p[3] = f2tf32(v.w);
        }
        // B tile 32x128: 1024 float4 / 256 thr = 4 each
#pragma unroll
        for (int q = 0; q < 4; ++q) {
            int idx = tid + q * 256;
            int k = idx >> 5;
            int j4 = (idx & 31) * 4;
            float4 v = *(const float4*)(W1 + (size_t)term * D * D + (size_t)(coff + k) * D + j4);
            uint32_t* p = &Bs[k * (128 + BPAD) + j4];
            p[0] = f2tf32(v.x); p[1] = f2tf32(v.y);
            p[2] = f2tf32(v.z); p[3] = f2tf32(v.w);
        }
        __syncthreads();

#pragma unroll
        for (int ks = 0; ks < 4; ++ks) {
            int k0 = ks * 8;
            uint32_t a[2][4];
#pragma unroll
            for (int mt = 0; mt < 2; ++mt) {
                int r = wm * 32 + mt * 16 + g;
                const uint32_t* ar = &As[r * (32 + APAD)];
                a[mt][0] = ar[k0 + tq];
                a[mt][1] = ar[8 * (32 + APAD) + k0 + tq];
                a[mt][2] = ar[k0 + tq + 4];
                a[mt][3] = ar[8 * (32 + APAD) + k0 + tq + 4];
            }
#pragma unroll
            for (int nt = 0; nt < 8; ++nt) {
                int cc = wn * 64 + nt * 8 + g;
                uint32_t b0 = Bs[(k0 + tq) * (128 + BPAD) + cc];
                uint32_t b1r = Bs[(k0 + tq + 4) * (128 + BPAD) + cc];
#pragma unroll
                for (int mt = 0; mt < 2; ++mt) {
                    asm volatile(
                        "mma.sync.aligned.m16n8k8.row.col.f32.tf32.tf32.f32 "
                        "{%0,%1,%2,%3}, {%4,%5,%6,%7}, {%8,%9}, {%0,%1,%2,%3};\n"
                        : "+f"(c[mt][nt][0]), "+f"(c[mt][nt][1]),
                          "+f"(c[mt][nt][2]), "+f"(c[mt][nt][3])
                        : "r"(a[mt][0]), "r"(a[mt][1]), "r"(a[mt][2]), "r"(a[mt][3]),
                          "r"(b0), "r"(b1r));
                }
            }
        }
        __syncthreads();
    }

    // epilogue: +bias, relu, store float2
#pragma unroll
    for (int mt = 0; mt < 2; ++mt) {
#pragma unroll
        for (int nt = 0; nt < 8; ++nt) {
            int col = wn * 64 + nt * 8 + 2 * tq;
            float bb0 = bsh[col], bb1 = bsh[col + 1];
            int r0 = row0 + wm * 32 + mt * 16 + g;
            if (r0 < n) {
                float2 v0 = make_float2(fmaxf(c[mt][nt][0] + bb0, 0.f),
                                        fmaxf(c[mt][nt][1] + bb1, 0.f));
                *(float2*)(g_h + (size_t)r0 * D + col) = v0;
            }
            int r1 = r0 + 8;
            if (r1 < n) {
                float2 v1 = make_float2(fmaxf(c[mt][nt][2] + bb0, 0.f),
                                        fmaxf(c[mt][nt][3] + bb1, 0.f));
                *(float2*)(g_h + (size_t)r1 * D + col) = v1;
            }
        }
    }
}

// ---------------- layer-2 GEMM + log_softmax ----------------
__global__ void k_gemm2(const float* __restrict__ W2, const float* __restrict__ b2,
                        float* __restrict__ out, int n) {
    __shared__ float As[32][33];
    __shared__ float Ws[32][40];
    __shared__ float zs[32][40];
    __shared__ float rl[32];

    int tid = threadIdx.x;
    int g = tid / 40;
    int j = tid % 40;
    int row0 = blockIdx.x * 32;

    const float* Aptr[3] = { g_h, g_tx1, g_tx2 };

    float acc[8];
#pragma unroll
    for (int r = 0; r < 8; ++r) acc[r] = 0.0f;

    for (int ch = 0; ch < 12; ++ch) {
        int term = ch >> 2;
        int coff = (ch & 3) * 32;
        const float* A = Aptr[term];

        for (int idx = tid; idx < 32 * 32; idx += 160) {
            int r = idx >> 5;
            int c = idx & 31;
            int grow = row0 + r;
            As[r][c] = (grow < n) ? A[(size_t)grow * D + coff + c] : 0.0f;
        }
        for (int idx = tid; idx < 32 * 40; idx += 160) {
            int k = idx / 40;
            int jj = idx % 40;
            Ws[k][jj] = W2[(size_t)term * D * C + (size_t)(coff + k) * C + jj];
        }
        __syncthreads();

#pragma unroll
        for (int k = 0; k < 32; ++k) {
            float w = Ws[k][j];
#pragma unroll
            for (int r = 0; r < 8; ++r) acc[r] += As[g * 8 + r][k] * w;
        }
        __syncthreads();
    }

    float bj = b2[j];
#pragma unroll
    for (int r = 0; r < 8; ++r) zs[g * 8 + r][j] = acc[r] + bj;
    __syncthreads();

    if (tid < 32) {
        float m = -INFINITY;
#pragma unroll
        for (int jj = 0; jj < C; ++jj) m = fmaxf(m, zs[tid][jj]);
        float s = 0.0f;
#pragma unroll
        for (int jj = 0; jj < C; ++jj) s += __expf(zs[tid][jj] - m);
        rl[tid] = m + logf(s);
    }
    __syncthreads();

#pragma unroll
    for (int r = 0; r < 8; ++r) {
        int lr = g * 8 + r;
        int grow = row0 + lr;
        if (grow < n) out[(size_t)grow * C + j] = zs[lr][j] - rl[lr];
    }
}

static float* sym_addr_f(const void* sym) {
    void* p = nullptr;
    cudaGetSymbolAddress(&p, sym);
    return (float*)p;
}

extern "C" void kernel_launch(void* const* d_in, const int* in_sizes, int n_in,
                              void* d_out, int out_size) {
    const float* x  = (const float*)d_in[0];
    const int*   ei = (const int*)d_in[1];
    const float* W1 = (const float*)d_in[2];
    const float* b1 = (const float*)d_in[3];
    const float* W2 = (const float*)d_in[4];
    const float* b2 = (const float*)d_in[5];
    float*       out = (float*)d_out;

    int N = in_sizes[0] / D;
    int E = in_sizes[1] / 2;

    float* tx1 = sym_addr_f((const void*)g_tx1);
    float* tx2 = sym_addr_f((const void*)g_tx2);
    float* h   = sym_addr_f((const void*)g_h);

    dim3 b256(256);
    int gN  = (N + 255) / 256;
    int gE  = (E + 255) / 256;
    int gSp = (N * 32 + 255) / 256;
    int gG1 = (N + 127) / 128;
    int gG2 = (N + 31) / 32;
    int nb  = (N + 1023) / 1024;

    // graph prep
    k_zero<<<gN, b256>>>(N);
    k_count<<<gE, b256>>>(ei, E);
    k_dinv<<<gN, b256>>>(N);
    k_scan1<<<nb, b256>>>(N);
    k_scan2<<<1, 32>>>(nb, N);
    k_scan3<<<nb, b256>>>(N);
    k_scatter<<<gE, b256>>>(ei, E);

    // layer 1
    k_spmv<<<gSp, b256>>>(x,   tx1, nullptr, 1.0f, N);
    k_spmv<<<gSp, b256>>>(tx1, tx2, x,       2.0f, N);
    k_gemm1<<<gG1, b256>>>(x, W1, b1, N);

    // layer 2
    k_spmv<<<gSp, b256>>>(h,   tx1, nullptr, 1.0f, N);
    k_spmv<<<gSp, b256>>>(tx1, tx2, h,       2.0f, N);
    k_gemm2<<<gG2, dim3(160)>>>(W2, b2, out, N);
}

// round 6
// speedup vs baseline: 1.8771x; 1.2064x over previous
#include <cuda_runtime.h>
#include <cuda_fp16.h>
#include <math.h>
#include <stdint.h>

#define MAX_N 50000
#define MAX_E 800000
#define D 128
#define C 40
#define NB 64

// ---------------- static scratch ----------------
__device__ int   g_cnt[MAX_N];
__device__ int   g_degc[MAX_N];
__device__ int   g_rowptr[MAX_N + 1];
__device__ int   g_off[MAX_N];
__device__ int   g_bsum[NB];
__device__ int   g_boff[NB];
__device__ int   g_csrc[MAX_E];
__device__ float g_csw[MAX_E];
__device__ float g_dinv[MAX_N];
// fp16 feature buffers (uint4 for 16B alignment)
__device__ uint4 g_x16_[MAX_N * D / 8];
__device__ uint4 g_tx1h_[MAX_N * D / 8];
__device__ uint4 g_tx2h_[MAX_N * D / 8];
__device__ uint4 g_hh_[MAX_N * D / 8];

__device__ __forceinline__ uint32_t f2tf32(float f) {
    uint32_t u;
    asm("cvt.rna.tf32.f32 %0, %1;" : "=r"(u) : "f"(f));
    return u;
}

// ---------------- graph prep ----------------
__global__ void k_zero(int n) {
    int i = blockIdx.x * blockDim.x + threadIdx.x;
    if (i < n) { g_cnt[i] = 0; g_degc[i] = 0; }
}

__global__ void k_count(const int* __restrict__ ei, int E) {
    int e = blockIdx.x * blockDim.x + threadIdx.x;
    if (e < E) {
        atomicAdd(&g_degc[ei[e]], 1);
        atomicAdd(&g_cnt[ei[E + e]], 1);
    }
}

__global__ void k_dinv(int n) {
    int i = blockIdx.x * blockDim.x + threadIdx.x;
    if (i < n) {
        int d = g_degc[i];
        g_dinv[i] = (d > 0) ? rsqrtf((float)d) : 0.0f;
    }
}

__global__ void k_scan1(int n) {
    int b = blockIdx.x, t = threadIdx.x;
    int base = b * 1024 + t * 4;
    int s = 0;
#pragma unroll
    for (int j = 0; j < 4; ++j) {
        int i = base + j;
        if (i < n) s += g_cnt[i];
    }
#pragma unroll
    for (int o = 16; o; o >>= 1) s += __shfl_down_sync(0xffffffffu, s, o);
    __shared__ int ws[8];
    if ((t & 31) == 0) ws[t >> 5] = s;
    __syncthreads();
    if (t == 0) {
        int tot = 0;
#pragma unroll
        for (int w = 0; w < 8; ++w) tot += ws[w];
        g_bsum[b] = tot;
    }
}

__global__ void k_scan2(int nb, int n) {
    int t = threadIdx.x;
    int v0 = (2 * t < nb) ? g_bsum[2 * t] : 0;
    int v1 = (2 * t + 1 < nb) ? g_bsum[2 * t + 1] : 0;
    int s = v0 + v1;
    int inc = s;
#pragma unroll
    for (int o = 1; o < 32; o <<= 1) {
        int u = __shfl_up_sync(0xffffffffu, inc, o);
        if (t >= o) inc += u;
    }
    int exc = inc - s;
    if (2 * t < nb) g_boff[2 * t] = exc;
    if (2 * t + 1 < nb) g_boff[2 * t + 1] = exc + v0;
    if (t == 31) g_rowptr[n] = inc;
}

__global__ void k_scan3(int n) {
    int b = blockIdx.x, t = threadIdx.x;
    int base = b * 1024 + t * 4;
    int v[4];
    int s = 0;
#pragma unroll
    for (int j = 0; j < 4; ++j) {
        int i = base + j;
        v[j] = (i < n) ? g_cnt[i] : 0;
        s += v[j];
    }
    int inc = s;
#pragma unroll
    for (int o = 1; o < 32; o <<= 1) {
        int u = __shfl_up_sync(0xffffffffu, inc, o);
        if ((t & 31) >= o) inc += u;
    }
    __shared__ int ws[8];
    __shared__ int wo[8];
    if ((t & 31) == 31) ws[t >> 5] = inc;
    __syncthreads();
    if (t == 0) {
        int p = 0;
#pragma unroll
        for (int w = 0; w < 8; ++w) { wo[w] = p; p += ws[w]; }
    }
    __syncthreads();
    int pre = g_boff[b] + wo[t >> 5] + (inc - s);
#pragma unroll
    for (int j = 0; j < 4; ++j) {
        int i = base + j;
        if (i < n) { g_rowptr[i] = pre; g_off[i] = pre; }
        pre += v[j];
    }
}

__global__ void k_scatter(const int* __restrict__ ei, int E) {
    int e = blockIdx.x * blockDim.x + threadIdx.x;
    if (e < E) {
        int s = ei[e];
        int t = ei[E + e];
        int p = atomicAdd(&g_off[t], 1);
        g_csrc[p] = s;
        g_csw[p] = -g_dinv[s] * g_dinv[t];
    }
}

// ---------------- fp32 -> fp16 convert (4 elems/thread) ----------------
__global__ void k_tohalf(const float* __restrict__ src, __half* __restrict__ dst, int n4) {
    int i = blockIdx.x * blockDim.x + threadIdx.x;
    if (i < n4) {
        float4 v = ((const float4*)src)[i];
        __half2 h0 = __floats2half2_rn(v.x, v.y);
        __half2 h1 = __floats2half2_rn(v.z, v.w);
        uint2 o;
        o.x = *(uint32_t*)&h0;
        o.y = *(uint32_t*)&h1;
        *(uint2*)(dst + (size_t)i * 4) = o;
    }
}

// ---------------- SpMV (CSR gather, fp16 features, fp32 accumulate) ----------------
// One warp per node; lane covers halves [4l, 4l+4) (8 B uint2 per lane per edge).
__global__ void k_spmv_h(const __half* __restrict__ hin, __half* __restrict__ hout,
                         const __half* __restrict__ sub, float scale, int n) {
    int node = blockIdx.x * (blockDim.x >> 5) + (threadIdx.x >> 5);
    int lane = threadIdx.x & 31;
    if (node >= n) return;
    int beg = g_rowptr[node];
    int end = g_rowptr[node + 1];
    float4 acc = make_float4(0.f, 0.f, 0.f, 0.f);
    for (int j = beg; j < end; ++j) {
        int s = g_csrc[j];
        float w = g_csw[j];
        uint2 u = *(const uint2*)(hin + (size_t)s * D + lane * 4);
        __half2 h0 = *(__half2*)&u.x;
        __half2 h1 = *(__half2*)&u.y;
        float2 f0 = __half22float2(h0);
        float2 f1 = __half22float2(h1);
        acc.x += w * f0.x; acc.y += w * f0.y;
        acc.z += w * f1.x; acc.w += w * f1.y;
    }
    float4 r;
    if (sub) {
        uint2 u = *(const uint2*)(sub + (size_t)node * D + lane * 4);
        __half2 h0 = *(__half2*)&u.x;
        __half2 h1 = *(__half2*)&u.y;
        float2 f0 = __half22float2(h0);
        float2 f1 = __half22float2(h1);
        r = make_float4(scale * acc.x - f0.x, scale * acc.y - f0.y,
                        scale * acc.z - f1.x, scale * acc.w - f1.y);
    } else {
        r = acc;
    }
    __half2 o0 = __floats2half2_rn(r.x, r.y);
    __half2 o1 = __floats2half2_rn(r.z, r.w);
    uint2 o;
    o.x = *(uint32_t*)&o0;
    o.y = *(uint32_t*)&o1;
    *(uint2*)(hout + (size_t)node * D + lane * 4) = o;
}

// ---------------- layer-1 GEMM: tf32 tensor cores ----------------
// h = relu([x|Tx1|Tx2] @ W1cat + b1).  x fp32; Tx1/Tx2 fp16. Output h fp16.
#define APAD 4
#define BPAD 8

__global__ void k_gemm1(const float* __restrict__ x, const float* __restrict__ W1,
                        const float* __restrict__ b1, int n) {
    __shared__ uint32_t As[128 * (32 + APAD)];
    __shared__ uint32_t Bs[32 * (128 + BPAD)];
    __shared__ float bsh[128];

    int tid = threadIdx.x;
    int wid = tid >> 5, lane = tid & 31;
    int wm = wid >> 1;
    int wn = wid & 1;
    int g = lane >> 2, tq = lane & 3;
    int row0 = blockIdx.x * 128;

    if (tid < 128) bsh[tid] = b1[tid];

    __half* hh = (__half*)g_hh_;

    float c[2][8][4];
#pragma unroll
    for (int mt = 0; mt < 2; ++mt)
#pragma unroll
        for (int nt = 0; nt < 8; ++nt)
#pragma unroll
            for (int q = 0; q < 4; ++q) c[mt][nt][q] = 0.0f;

    for (int ch = 0; ch < 12; ++ch) {
        int term = ch >> 2;
        int coff = (ch & 3) * 32;

        // A tile 128x32
#pragma unroll
        for (int q = 0; q < 4; ++q) {
            int idx = tid + q * 256;
            int r = idx >> 3;
            int c4 = (idx & 7) * 4;
            int grow = row0 + r;
            float4 v;
            if (term == 0) {
                v = (grow < n)
                    ? *(const float4*)(x + (size_t)grow * D + coff + c4)
                    : make_float4(0.f, 0.f, 0.f, 0.f);
            } else {
                const __half* A16 = (term == 1) ? (const __half*)g_tx1h_
                                                : (const __half*)g_tx2h_;
                if (grow < n) {
                    uint2 u = *(const uint2*)(A16 + (size_t)grow * D + coff + c4);
                    __half2 h0 = *(__half2*)&u.x;
                    __half2 h1 = *(__half2*)&u.y;
                    float2 f0 = __half22float2(h0);
                    float2 f1 = __half22float2(h1);
                    v = make_float4(f0.x, f0.y, f1.x, f1.y);
                } else {
                    v = make_float4(0.f, 0.f, 0.f, 0.f);
                }
            }
            uint32_t* p = &As[r * (32 + APAD) + c4];
            p[0] = f2tf32(v.x); p[1] = f2tf32(v.y);
            p[2] = f2tf32(v.z); p[3] = f2tf32(v.w);
        }
        // B tile 32x128
#pragma unroll
        for (int q = 0; q < 4; ++q) {
            int idx = tid + q * 256;
            int k = idx >> 5;
            int j4 = (idx & 31) * 4;
            float4 v = *(const float4*)(W1 + (size_t)term * D * D + (size_t)(coff + k) * D + j4);
            uint32_t* p = &Bs[k * (128 + BPAD) + j4];
            p[0] = f2tf32(v.x); p[1] = f2tf32(v.y);
            p[2] = f2tf32(v.z); p[3] = f2tf32(v.w);
        }
        __syncthreads();

#pragma unroll
        for (int ks = 0; ks < 4; ++ks) {
            int k0 = ks * 8;
            uint32_t a[2][4];
#pragma unroll
            for (int mt = 0; mt < 2; ++mt) {
                int r = wm * 32 + mt * 16 + g;
                const uint32_t* ar = &As[r * (32 + APAD)];
                a[mt][0] = ar[k0 + tq];
                a[mt][1] = ar[8 * (32 + APAD) + k0 + tq];
                a[mt][2] = ar[k0 + tq + 4];
                a[mt][3] = ar[8 * (32 + APAD) + k0 + tq + 4];
            }
#pragma unroll
            for (int nt = 0; nt < 8; ++nt) {
                int cc = wn * 64 + nt * 8 + g;
                uint32_t b0 = Bs[(k0 + tq) * (128 + BPAD) + cc];
                uint32_t b1r = Bs[(k0 + tq + 4) * (128 + BPAD) + cc];
#pragma unroll
                for (int mt = 0; mt < 2; ++mt) {
                    asm volatile(
                        "mma.sync.aligned.m16n8k8.row.col.f32.tf32.tf32.f32 "
                        "{%0,%1,%2,%3}, {%4,%5,%6,%7}, {%8,%9}, {%0,%1,%2,%3};\n"
                        : "+f"(c[mt][nt][0]), "+f"(c[mt][nt][1]),
                          "+f"(c[mt][nt][2]), "+f"(c[mt][nt][3])
                        : "r"(a[mt][0]), "r"(a[mt][1]), "r"(a[mt][2]), "r"(a[mt][3]),
                          "r"(b0), "r"(b1r));
                }
            }
        }
        __syncthreads();
    }

    // epilogue: +bias, relu, store fp16 (half2 per 2 cols)
#pragma unroll
    for (int mt = 0; mt < 2; ++mt) {
#pragma unroll
        for (int nt = 0; nt < 8; ++nt) {
            int col = wn * 64 + nt * 8 + 2 * tq;
            float bb0 = bsh[col], bb1 = bsh[col + 1];
            int r0 = row0 + wm * 32 + mt * 16 + g;
            if (r0 < n) {
                __half2 v0 = __floats2half2_rn(fmaxf(c[mt][nt][0] + bb0, 0.f),
                                               fmaxf(c[mt][nt][1] + bb1, 0.f));
                *(__half2*)(hh + (size_t)r0 * D + col) = v0;
            }
            int r1 = r0 + 8;
            if (r1 < n) {
                __half2 v1 = __floats2half2_rn(fmaxf(c[mt][nt][2] + bb0, 0.f),
                                               fmaxf(c[mt][nt][3] + bb1, 0.f));
                *(__half2*)(hh + (size_t)r1 * D + col) = v1;
            }
        }
    }
}

// ---------------- layer-2 GEMM + log_softmax (fp16 A, fp32 compute) ----------------
__global__ void k_gemm2(const float* __restrict__ W2, const float* __restrict__ b2,
                        float* __restrict__ out, int n) {
    __shared__ float As[32][33];
    __shared__ float Ws[32][40];
    __shared__ float zs[32][40];
    __shared__ float rl[32];

    int tid = threadIdx.x;
    int g = tid / 40;
    int j = tid % 40;
    int row0 = blockIdx.x * 32;

    float acc[8];
#pragma unroll
    for (int r = 0; r < 8; ++r) acc[r] = 0.0f;

    for (int ch = 0; ch < 12; ++ch) {
        int term = ch >> 2;
        int coff = (ch & 3) * 32;
        const __half* A = (term == 0) ? (const __half*)g_hh_
                        : (term == 1) ? (const __half*)g_tx1h_
                                      : (const __half*)g_tx2h_;

        for (int idx = tid; idx < 32 * 32; idx += 160) {
            int r = idx >> 5;
            int c = idx & 31;
            int grow = row0 + r;
            As[r][c] = (grow < n) ? __half2float(A[(size_t)grow * D + coff + c]) : 0.0f;
        }
        for (int idx = tid; idx < 32 * 40; idx += 160) {
            int k = idx / 40;
            int jj = idx % 40;
            Ws[k][jj] = W2[(size_t)term * D * C + (size_t)(coff + k) * C + jj];
        }
        __syncthreads();

#pragma unroll
        for (int k = 0; k < 32; ++k) {
            float w = Ws[k][j];
#pragma unroll
            for (int r = 0; r < 8; ++r) acc[r] += As[g * 8 + r][k] * w;
        }
        __syncthreads();
    }

    float bj = b2[j];
#pragma unroll
    for (int r = 0; r < 8; ++r) zs[g * 8 + r][j] = acc[r] + bj;
    __syncthreads();

    if (tid < 32) {
        float m = -INFINITY;
#pragma unroll
        for (int jj = 0; jj < C; ++jj) m = fmaxf(m, zs[tid][jj]);
        float s = 0.0f;
#pragma unroll
        for (int jj = 0; jj < C; ++jj) s += __expf(zs[tid][jj] - m);
        rl[tid] = m + logf(s);
    }
    __syncthreads();

#pragma unroll
    for (int r = 0; r < 8; ++r) {
        int lr = g * 8 + r;
        int grow = row0 + lr;
        if (grow < n) out[(size_t)grow * C + j] = zs[lr][j] - rl[lr];
    }
}

static void* sym_addr(const void* sym) {
    void* p = nullptr;
    cudaGetSymbolAddress(&p, sym);
    return p;
}

extern "C" void kernel_launch(void* const* d_in, const int* in_sizes, int n_in,
                              void* d_out, int out_size) {
    const float* x  = (const float*)d_in[0];
    const int*   ei = (const int*)d_in[1];
    const float* W1 = (const float*)d_in[2];
    const float* b1 = (const float*)d_in[3];
    const float* W2 = (const float*)d_in[4];
    const float* b2 = (const float*)d_in[5];
    float*       out = (float*)d_out;

    int N = in_sizes[0] / D;
    int E = in_sizes[1] / 2;
    int n4 = N * D / 4;

    __half* x16  = (__half*)sym_addr((const void*)g_x16_);
    __half* tx1h = (__half*)sym_addr((const void*)g_tx1h_);
    __half* tx2h = (__half*)sym_addr((const void*)g_tx2h_);
    __half* hh   = (__half*)sym_addr((const void*)g_hh_);

    dim3 b256(256);
    int gN  = (N + 255) / 256;
    int gE  = (E + 255) / 256;
    int gN4 = (n4 + 255) / 256;
    int gSp = (N * 32 + 255) / 256;
    int gG1 = (N + 127) / 128;
    int gG2 = (N + 31) / 32;
    int nb  = (N + 1023) / 1024;

    // graph prep
    k_zero<<<gN, b256>>>(N);
    k_count<<<gE, b256>>>(ei, E);
    k_dinv<<<gN, b256>>>(N);
    k_scan1<<<nb, b256>>>(N);
    k_scan2<<<1, 32>>>(nb, N);
    k_scan3<<<nb, b256>>>(N);
    k_scatter<<<gE, b256>>>(ei, E);

    // layer 1: x16 = half(x); Tx1 = L~ x16 ; Tx2 = 2 L~ Tx1 - x16
    k_tohalf<<<gN4, b256>>>(x, x16, n4);
    k_spmv_h<<<gSp, b256>>>(x16,  tx1h, nullptr, 1.0f, N);
    k_spmv_h<<<gSp, b256>>>(tx1h, tx2h, x16,     2.0f, N);
    k_gemm1<<<gG1, b256>>>(x, W1, b1, N);

    // layer 2: Tx1 = L~ h ; Tx2 = 2 L~ Tx1 - h
    k_spmv_h<<<gSp, b256>>>(hh,   tx1h, nullptr, 1.0f, N);
    k_spmv_h<<<gSp, b256>>>(tx1h, tx2h, hh,      2.0f, N);
    k_gemm2<<<gG2, dim3(160)>>>(W2, b2, out, N);
}

// round 7
// speedup vs baseline: 2.5376x; 1.3519x over previous
#include <cuda_runtime.h>
#include <cuda_fp16.h>
#include <math.h>
#include <stdint.h>

#define MAX_N 50000
#define MAX_E 800000
#define D 128
#define C 40
#define NB 64

// ---------------- static scratch ----------------
__device__ int   g_cnt[MAX_N];
__device__ int   g_degc[MAX_N];
__device__ int   g_rowptr[MAX_N + 1];
__device__ int   g_off[MAX_N];
__device__ int   g_bsum[NB];
__device__ int   g_boff[NB];
__device__ int   g_csrc[MAX_E];
__device__ float g_csw[MAX_E];
__device__ float g_dinv[MAX_N];
// fp16 feature buffers (uint4 for 16B alignment)
__device__ uint4 g_x16_[MAX_N * D / 8];
__device__ uint4 g_tx1h_[MAX_N * D / 8];
__device__ uint4 g_tx2h_[MAX_N * D / 8];
__device__ uint4 g_hh_[MAX_N * D / 8];
// W2^T fp16: [40][384] (term-major k)
__device__ uint4 g_w2t_[40 * 384 / 8];

__device__ __forceinline__ uint32_t f2tf32(float f) {
    uint32_t u;
    asm("cvt.rna.tf32.f32 %0, %1;" : "=r"(u) : "f"(f));
    return u;
}

// ---------------- graph prep ----------------
__global__ void k_zero(int n) {
    int i = blockIdx.x * blockDim.x + threadIdx.x;
    if (i < n) { g_cnt[i] = 0; g_degc[i] = 0; }
}

__global__ void k_count(const int* __restrict__ ei, int E) {
    int e = blockIdx.x * blockDim.x + threadIdx.x;
    if (e < E) {
        atomicAdd(&g_degc[ei[e]], 1);
        atomicAdd(&g_cnt[ei[E + e]], 1);
    }
}

__global__ void k_dinv(int n) {
    int i = blockIdx.x * blockDim.x + threadIdx.x;
    if (i < n) {
        int d = g_degc[i];
        g_dinv[i] = (d > 0) ? rsqrtf((float)d) : 0.0f;
    }
}

__global__ void k_scan1(int n) {
    int b = blockIdx.x, t = threadIdx.x;
    int base = b * 1024 + t * 4;
    int s = 0;
#pragma unroll
    for (int j = 0; j < 4; ++j) {
        int i = base + j;
        if (i < n) s += g_cnt[i];
    }
#pragma unroll
    for (int o = 16; o; o >>= 1) s += __shfl_down_sync(0xffffffffu, s, o);
    __shared__ int ws[8];
    if ((t & 31) == 0) ws[t >> 5] = s;
    __syncthreads();
    if (t == 0) {
        int tot = 0;
#pragma unroll
        for (int w = 0; w < 8; ++w) tot += ws[w];
        g_bsum[b] = tot;
    }
}

__global__ void k_scan2(int nb, int n) {
    int t = threadIdx.x;
    int v0 = (2 * t < nb) ? g_bsum[2 * t] : 0;
    int v1 = (2 * t + 1 < nb) ? g_bsum[2 * t + 1] : 0;
    int s = v0 + v1;
    int inc = s;
#pragma unroll
    for (int o = 1; o < 32; o <<= 1) {
        int u = __shfl_up_sync(0xffffffffu, inc, o);
        if (t >= o) inc += u;
    }
    int exc = inc - s;
    if (2 * t < nb) g_boff[2 * t] = exc;
    if (2 * t + 1 < nb) g_boff[2 * t + 1] = exc + v0;
    if (t == 31) g_rowptr[n] = inc;
}

__global__ void k_scan3(int n) {
    int b = blockIdx.x, t = threadIdx.x;
    int base = b * 1024 + t * 4;
    int v[4];
    int s = 0;
#pragma unroll
    for (int j = 0; j < 4; ++j) {
        int i = base + j;
        v[j] = (i < n) ? g_cnt[i] : 0;
        s += v[j];
    }
    int inc = s;
#pragma unroll
    for (int o = 1; o < 32; o <<= 1) {
        int u = __shfl_up_sync(0xffffffffu, inc, o);
        if ((t & 31) >= o) inc += u;
    }
    __shared__ int ws[8];
    __shared__ int wo[8];
    if ((t & 31) == 31) ws[t >> 5] = inc;
    __syncthreads();
    if (t == 0) {
        int p = 0;
#pragma unroll
        for (int w = 0; w < 8; ++w) { wo[w] = p; p += ws[w]; }
    }
    __syncthreads();
    int pre = g_boff[b] + wo[t >> 5] + (inc - s);
#pragma unroll
    for (int j = 0; j < 4; ++j) {
        int i = base + j;
        if (i < n) { g_rowptr[i] = pre; g_off[i] = pre; }
        pre += v[j];
    }
}

__global__ void k_scatter(const int* __restrict__ ei, int E) {
    int e = blockIdx.x * blockDim.x + threadIdx.x;
    if (e < E) {
        int s = ei[e];
        int t = ei[E + e];
        int p = atomicAdd(&g_off[t], 1);
        g_csrc[p] = s;
        g_csw[p] = -g_dinv[s] * g_dinv[t];
    }
}

// ---------------- fp32 -> fp16 convert ----------------
__global__ void k_tohalf(const float* __restrict__ src, __half* __restrict__ dst, int n4) {
    int i = blockIdx.x * blockDim.x + threadIdx.x;
    if (i < n4) {
        float4 v = ((const float4*)src)[i];
        __half2 h0 = __floats2half2_rn(v.x, v.y);
        __half2 h1 = __floats2half2_rn(v.z, v.w);
        uint2 o;
        o.x = *(uint32_t*)&h0;
        o.y = *(uint32_t*)&h1;
        *(uint2*)(dst + (size_t)i * 4) = o;
    }
}

// W2^T fp16: W2T[n][term*128+k] = W2[term][k][n]
__global__ void k_w2t(const float* __restrict__ W2) {
    int i = blockIdx.x * blockDim.x + threadIdx.x;   // 15360
    if (i < 3 * 128 * C) {
        int n = i / 384;
        int r = i % 384;
        int term = r >> 7;
        int k = r & 127;
        ((__half*)g_w2t_)[i] = __float2half(W2[(size_t)term * 128 * C + (size_t)k * C + n]);
    }
}

// ---------------- SpMV: CSR gather, 2 edges/iter split-warp ----------------
// Lanes 0-15 = edge j, lanes 16-31 = edge j+1. Lane covers halves [8*hl, 8*hl+8).
__global__ void k_spmv_h(const __half* __restrict__ hin, __half* __restrict__ hout,
                         const __half* __restrict__ sub, float scale, int n) {
    int node = blockIdx.x * (blockDim.x >> 5) + (threadIdx.x >> 5);
    int lane = threadIdx.x & 31;
    int half = lane >> 4;
    int hl = lane & 15;
    if (node >= n) return;
    int beg = g_rowptr[node];
    int end = g_rowptr[node + 1];
    float acc[8];
#pragma unroll
    for (int q = 0; q < 8; ++q) acc[q] = 0.0f;

    for (int j = beg; j < end; j += 2) {
        int jj = j + half;
        if (jj < end) {
            int s = __ldg(&g_csrc[jj]);
            float w = __ldg(&g_csw[jj]);
            uint4 u = *(const uint4*)(hin + (size_t)s * D + hl * 8);
            float2 f0 = __half22float2(*(__half2*)&u.x);
            float2 f1 = __half22float2(*(__half2*)&u.y);
            float2 f2 = __half22float2(*(__half2*)&u.z);
            float2 f3 = __half22float2(*(__half2*)&u.w);
            acc[0] += w * f0.x; acc[1] += w * f0.y;
            acc[2] += w * f1.x; acc[3] += w * f1.y;
            acc[4] += w * f2.x; acc[5] += w * f2.y;
            acc[6] += w * f3.x; acc[7] += w * f3.y;
        }
    }
    // combine the two edge-halves
#pragma unroll
    for (int q = 0; q < 8; ++q)
        acc[q] += __shfl_xor_sync(0xffffffffu, acc[q], 16);

    if (half == 0) {
        float r[8];
        if (sub) {
            uint4 u = *(const uint4*)(sub + (size_t)node * D + hl * 8);
            float2 f0 = __half22float2(*(__half2*)&u.x);
            float2 f1 = __half22float2(*(__half2*)&u.y);
            float2 f2 = __half22float2(*(__half2*)&u.z);
            float2 f3 = __half22float2(*(__half2*)&u.w);
            r[0] = scale * acc[0] - f0.x; r[1] = scale * acc[1] - f0.y;
            r[2] = scale * acc[2] - f1.x; r[3] = scale * acc[3] - f1.y;
            r[4] = scale * acc[4] - f2.x; r[5] = scale * acc[5] - f2.y;
            r[6] = scale * acc[6] - f3.x; r[7] = scale * acc[7] - f3.y;
        } else {
#pragma unroll
            for (int q = 0; q < 8; ++q) r[q] = acc[q];
        }
        __half2 h0 = __floats2half2_rn(r[0], r[1]);
        __half2 h1 = __floats2half2_rn(r[2], r[3]);
        __half2 h2 = __floats2half2_rn(r[4], r[5]);
        __half2 h3 = __floats2half2_rn(r[6], r[7]);
        uint4 o;
        o.x = *(uint32_t*)&h0; o.y = *(uint32_t*)&h1;
        o.z = *(uint32_t*)&h2; o.w = *(uint32_t*)&h3;
        *(uint4*)(hout + (size_t)node * D + hl * 8) = o;
    }
}

// ---------------- layer-1 GEMM: tf32 tensor cores ----------------
#define APAD 4
#define BPAD 8

__global__ void k_gemm1(const float* __restrict__ x, const float* __restrict__ W1,
                        const float* __restrict__ b1, int n) {
    __shared__ uint32_t As[128 * (32 + APAD)];
    __shared__ uint32_t Bs[32 * (128 + BPAD)];
    __shared__ float bsh[128];

    int tid = threadIdx.x;
    int wid = tid >> 5, lane = tid & 31;
    int wm = wid >> 1;
    int wn = wid & 1;
    int g = lane >> 2, tq = lane & 3;
    int row0 = blockIdx.x * 128;

    if (tid < 128) bsh[tid] = b1[tid];

    __half* hh = (__half*)g_hh_;

    float c[2][8][4];
#pragma unroll
    for (int mt = 0; mt < 2; ++mt)
#pragma unroll
        for (int nt = 0; nt < 8; ++nt)
#pragma unroll
            for (int q = 0; q < 4; ++q) c[mt][nt][q] = 0.0f;

    for (int ch = 0; ch < 12; ++ch) {
        int term = ch >> 2;
        int coff = (ch & 3) * 32;

#pragma unroll
        for (int q = 0; q < 4; ++q) {
            int idx = tid + q * 256;
            int r = idx >> 3;
            int c4 = (idx & 7) * 4;
            int grow = row0 + r;
            float4 v;
            if (term == 0) {
                v = (grow < n)
                    ? *(const float4*)(x + (size_t)grow * D + coff + c4)
                    : make_float4(0.f, 0.f, 0.f, 0.f);
            } else {
                const __half* A16 = (term == 1) ? (const __half*)g_tx1h_
                                                : (const __half*)g_tx2h_;
                if (grow < n) {
                    uint2 u = *(const uint2*)(A16 + (size_t)grow * D + coff + c4);
                    float2 f0 = __half22float2(*(__half2*)&u.x);
                    float2 f1 = __half22float2(*(__half2*)&u.y);
                    v = make_float4(f0.x, f0.y, f1.x, f1.y);
                } else {
                    v = make_float4(0.f, 0.f, 0.f, 0.f);
                }
            }
            uint32_t* p = &As[r * (32 + APAD) + c4];
            p[0] = f2tf32(v.x); p[1] = f2tf32(v.y);
            p[2] = f2tf32(v.z); p[3] = f2tf32(v.w);
        }
#pragma unroll
        for (int q = 0; q < 4; ++q) {
            int idx = tid + q * 256;
            int k = idx >> 5;
            int j4 = (idx & 31) * 4;
            float4 v = *(const float4*)(W1 + (size_t)term * D * D + (size_t)(coff + k) * D + j4);
            uint32_t* p = &Bs[k * (128 + BPAD) + j4];
            p[0] = f2tf32(v.x); p[1] = f2tf32(v.y);
            p[2] = f2tf32(v.z); p[3] = f2tf32(v.w);
        }
        __syncthreads();

#pragma unroll
        for (int ks = 0; ks < 4; ++ks) {
            int k0 = ks * 8;
            uint32_t a[2][4];
#pragma unroll
            for (int mt = 0; mt < 2; ++mt) {
                int r = wm * 32 + mt * 16 + g;
                const uint32_t* ar = &As[r * (32 + APAD)];
                a[mt][0] = ar[k0 + tq];
                a[mt][1] = ar[8 * (32 + APAD) + k0 + tq];
                a[mt][2] = ar[k0 + tq + 4];
                a[mt][3] = ar[8 * (32 + APAD) + k0 + tq + 4];
            }
#pragma unroll
            for (int nt = 0; nt < 8; ++nt) {
                int cc = wn * 64 + nt * 8 + g;
                uint32_t b0 = Bs[(k0 + tq) * (128 + BPAD) + cc];
                uint32_t b1r = Bs[(k0 + tq + 4) * (128 + BPAD) + cc];
#pragma unroll
                for (int mt = 0; mt < 2; ++mt) {
                    asm volatile(
                        "mma.sync.aligned.m16n8k8.row.col.f32.tf32.tf32.f32 "
                        "{%0,%1,%2,%3}, {%4,%5,%6,%7}, {%8,%9}, {%0,%1,%2,%3};\n"
                        : "+f"(c[mt][nt][0]), "+f"(c[mt][nt][1]),
                          "+f"(c[mt][nt][2]), "+f"(c[mt][nt][3])
                        : "r"(a[mt][0]), "r"(a[mt][1]), "r"(a[mt][2]), "r"(a[mt][3]),
                          "r"(b0), "r"(b1r));
                }
            }
        }
        __syncthreads();
    }

#pragma unroll
    for (int mt = 0; mt < 2; ++mt) {
#pragma unroll
        for (int nt = 0; nt < 8; ++nt) {
            int col = wn * 64 + nt * 8 + 2 * tq;
            float bb0 = bsh[col], bb1 = bsh[col + 1];
            int r0 = row0 + wm * 32 + mt * 16 + g;
            if (r0 < n) {
                __half2 v0 = __floats2half2_rn(fmaxf(c[mt][nt][0] + bb0, 0.f),
                                               fmaxf(c[mt][nt][1] + bb1, 0.f));
                *(__half2*)(hh + (size_t)r0 * D + col) = v0;
            }
            int r1 = r0 + 8;
            if (r1 < n) {
                __half2 v1 = __floats2half2_rn(fmaxf(c[mt][nt][2] + bb0, 0.f),
                                               fmaxf(c[mt][nt][3] + bb1, 0.f));
                *(__half2*)(hh + (size_t)r1 * D + col) = v1;
            }
        }
    }
}

// ---------------- layer-2 GEMM: fp16 mma + fused log_softmax ----------------
// out = log_softmax([h|Tx1|Tx2] @ W2cat + b2). 256 thr / 8 warps; warp = 16 rows.
// m16n8k16 fp16->f32; N=40 = 5 ntiles. A/B smem stride 40 halves (conflict-free frags).
#define S2 40

__global__ void k_gemm2(const float* __restrict__ b2, float* __restrict__ out, int n) {
    __shared__ __half As2[128 * S2];
    __shared__ __half Bs2[40 * S2];
    __shared__ float bsh[40];

    int tid = threadIdx.x;
    int wid = tid >> 5, lane = tid & 31;
    int g = lane >> 2, tq = lane & 3;
    int row0 = blockIdx.x * 128;

    if (tid < 40) bsh[tid] = b2[tid];

    const __half* w2t = (const __half*)g_w2t_;

    float c[5][4];
#pragma unroll
    for (int nt = 0; nt < 5; ++nt)
#pragma unroll
        for (int q = 0; q < 4; ++q) c[nt][q] = 0.0f;

    for (int ch = 0; ch < 12; ++ch) {
        int term = ch >> 2;
        int coff = (ch & 3) * 32;
        const __half* A = (term == 0) ? (const __half*)g_hh_
                        : (term == 1) ? (const __half*)g_tx1h_
                                      : (const __half*)g_tx2h_;

        // A tile 128x32 halves: 512 uint4 / 256 thr
#pragma unroll
        for (int q = 0; q < 2; ++q) {
            int idx = tid + q * 256;
            int r = idx >> 2;
            int c8 = (idx & 3) * 8;
            int grow = row0 + r;
            uint4 v = (grow < n)
                ? *(const uint4*)(A + (size_t)grow * D + coff + c8)
                : make_uint4(0u, 0u, 0u, 0u);
            *(uint4*)&As2[r * S2 + c8] = v;
        }
        // B tile 40x32 halves (row = n, col = k): 160 uint4
        if (tid < 160) {
            int r = tid >> 2;
            int c8 = (tid & 3) * 8;
            *(uint4*)&Bs2[r * S2 + c8] =
                *(const uint4*)(w2t + (size_t)r * 384 + term * 128 + coff + c8);
        }
        __syncthreads();

#pragma unroll
        for (int ks = 0; ks < 2; ++ks) {
            int kb = ks * 16;
            const __half* ar = &As2[(wid * 16 + g) * S2 + kb + 2 * tq];
            uint32_t a0 = *(const uint32_t*)ar;
            uint32_t a1 = *(const uint32_t*)(ar + 8 * S2);
            uint32_t a2 = *(const uint32_t*)(ar + 8);
            uint32_t a3 = *(const uint32_t*)(ar + 8 * S2 + 8);
#pragma unroll
            for (int nt = 0; nt < 5; ++nt) {
                const __half* br = &Bs2[(nt * 8 + g) * S2 + kb + 2 * tq];
                uint32_t b0 = *(const uint32_t*)br;
                uint32_t b1r = *(const uint32_t*)(br + 8);
                asm volatile(
                    "mma.sync.aligned.m16n8k16.row.col.f32.f16.f16.f32 "
                    "{%0,%1,%2,%3}, {%4,%5,%6,%7}, {%8,%9}, {%0,%1,%2,%3};\n"
                    : "+f"(c[nt][0]), "+f"(c[nt][1]), "+f"(c[nt][2]), "+f"(c[nt][3])
                    : "r"(a0), "r"(a1), "r"(a2), "r"(a3), "r"(b0), "r"(b1r));
            }
        }
        __syncthreads();
    }

    // epilogue: +bias, per-row log-sum-exp (quad shuffle), store
    float zz[5][4];
#pragma unroll
    for (int nt = 0; nt < 5; ++nt) {
        float bb0 = bsh[nt * 8 + 2 * tq];
        float bb1 = bsh[nt * 8 + 2 * tq + 1];
        zz[nt][0] = c[nt][0] + bb0;
        zz[nt][1] = c[nt][1] + bb1;
        zz[nt][2] = c[nt][2] + bb0;
        zz[nt][3] = c[nt][3] + bb1;
    }
    float m0 = -INFINITY, m1 = -INFINITY;
#pragma unroll
    for (int nt = 0; nt < 5; ++nt) {
        m0 = fmaxf(m0, fmaxf(zz[nt][0], zz[nt][1]));
        m1 = fmaxf(m1, fmaxf(zz[nt][2], zz[nt][3]));
    }
    m0 = fmaxf(m0, __shfl_xor_sync(0xffffffffu, m0, 1));
    m0 = fmaxf(m0, __shfl_xor_sync(0xffffffffu, m0, 2));
    m1 = fmaxf(m1, __shfl_xor_sync(0xffffffffu, m1, 1));
    m1 = fmaxf(m1, __shfl_xor_sync(0xffffffffu, m1, 2));
    float s0 = 0.0f, s1 = 0.0f;
#pragma unroll
    for (int nt = 0; nt < 5; ++nt) {
        s0 += __expf(zz[nt][0] - m0) + __expf(zz[nt][1] - m0);
        s1 += __expf(zz[nt][2] - m1) + __expf(zz[nt][3] - m1);
    }
    s0 += __shfl_xor_sync(0xffffffffu, s0, 1);
    s0 += __shfl_xor_sync(0xffffffffu, s0, 2);
    s1 += __shfl_xor_sync(0xffffffffu, s1, 1);
    s1 += __shfl_xor_sync(0xffffffffu, s1, 2);
    float lse0 = m0 + logf(s0);
    float lse1 = m1 + logf(s1);

    int r0 = row0 + wid * 16 + g;
    int r1 = r0 + 8;
#pragma unroll
    for (int nt = 0; nt < 5; ++nt) {
        int col = nt * 8 + 2 * tq;
        if (r0 < n)
            *(float2*)(out + (size_t)r0 * C + col) =
                make_float2(zz[nt][0] - lse0, zz[nt][1] - lse0);
        if (r1 < n)
            *(float2*)(out + (size_t)r1 * C + col) =
                make_float2(zz[nt][2] - lse1, zz[nt][3] - lse1);
    }
}

static void* sym_addr(const void* sym) {
    void* p = nullptr;
    cudaGetSymbolAddress(&p, sym);
    return p;
}

extern "C" void kernel_launch(void* const* d_in, const int* in_sizes, int n_in,
                              void* d_out, int out_size) {
    const float* x  = (const float*)d_in[0];
    const int*   ei = (const int*)d_in[1];
    const float* W1 = (const float*)d_in[2];
    const float* b1 = (const float*)d_in[3];
    const float* W2 = (const float*)d_in[4];
    const float* b2 = (const float*)d_in[5];
    float*       out = (float*)d_out;

    int N = in_sizes[0] / D;
    int E = in_sizes[1] / 2;
    int n4 = N * D / 4;

    __half* x16  = (__half*)sym_addr((const void*)g_x16_);
    __half* tx1h = (__half*)sym_addr((const void*)g_tx1h_);
    __half* tx2h = (__half*)sym_addr((const void*)g_tx2h_);
    __half* hh   = (__half*)sym_addr((const void*)g_hh_);

    dim3 b256(256);
    int gN  = (N + 255) / 256;
    int gE  = (E + 255) / 256;
    int gN4 = (n4 + 255) / 256;
    int gSp = (N * 32 + 255) / 256;
    int gG1 = (N + 127) / 128;
    int gG2 = (N + 127) / 128;
    int nb  = (N + 1023) / 1024;

    // graph prep
    k_zero<<<gN, b256>>>(N);
    k_count<<<gE, b256>>>(ei, E);
    k_dinv<<<gN, b256>>>(N);
    k_scan1<<<nb, b256>>>(N);
    k_scan2<<<1, 32>>>(nb, N);
    k_scan3<<<nb, b256>>>(N);
    k_scatter<<<gE, b256>>>(ei, E);
    k_w2t<<<(3 * 128 * C + 255) / 256, b256>>>(W2);

    // layer 1
    k_tohalf<<<gN4, b256>>>(x, x16, n4);
    k_spmv_h<<<gSp, b256>>>(x16,  tx1h, nullptr, 1.0f, N);
    k_spmv_h<<<gSp, b256>>>(tx1h, tx2h, x16,     2.0f, N);
    k_gemm1<<<gG1, b256>>>(x, W1, b1, N);

    // layer 2
    k_spmv_h<<<gSp, b256>>>(hh,   tx1h, nullptr, 1.0f, N);
    k_spmv_h<<<gSp, b256>>>(tx1h, tx2h, hh,      2.0f, N);
    k_gemm2<<<gG2, b256>>>(b2, out, N);
}